// round 6
// baseline (speedup 1.0000x reference)
#include <cuda_runtime.h>
#include <cstdint>

// GraphAttentionPooling: B=32, N=3072, F=256, P=3 -> 32768 windows of 3x256.
// Persistent 296 blocks (2/SM) x 256 threads. Each warp owns a private
// 4-slot smem ring (slot = one 3 KB window) filled with cp.async.cg,
// one commit-group per window, depth-3 in flight. Zero cross-warp sync:
// each lane copies and later reads exactly its own 6x16B of the window.

#define STAGES       4
#define WIN_FLOATS   768           // 3 rows * 256
#define WIN_BYTES    3072
#define RING_BYTES   (STAGES * WIN_BYTES)          // 12288 per warp
#define WARPS_PER_BLOCK 8
#define THREADS      (WARPS_PER_BLOCK * 32)
#define SMEM_BYTES   (WARPS_PER_BLOCK * RING_BYTES) // 98304
#define NUM_SMS      148
#define BLOCKS_PER_SM 2

__device__ __forceinline__ uint32_t smem_u32(const void* p) {
    uint32_t a;
    asm("{ .reg .u64 t; cvta.to.shared.u64 t, %1; cvt.u32.u64 %0, t; }"
        : "=r"(a) : "l"(p));
    return a;
}

__device__ __forceinline__ void cp16(uint32_t dst, const void* src) {
    asm volatile("cp.async.cg.shared.global [%0], [%1], 16;"
                 :: "r"(dst), "l"(src) : "memory");
}
__device__ __forceinline__ void cp_commit() {
    asm volatile("cp.async.commit_group;" ::: "memory");
}
__device__ __forceinline__ void cp_wait3() {
    asm volatile("cp.async.wait_group 3;" ::: "memory");
}

// Copy one 3 KB window (gmem, 16B-aligned) into a ring slot.
// Lane l copies bytes [16l,16l+16) of each 512B half-row (6 chunks).
__device__ __forceinline__ void issue_window(uint32_t slot_smem,
                                             const char* gwin, int lane) {
    const int off = lane * 16;
    #pragma unroll
    for (int c = 0; c < 6; c++) {
        cp16(slot_smem + c * 512 + off, gwin + c * 512 + off);
    }
    cp_commit();
}

__device__ __forceinline__ float warp_reduce_sum(float v) {
    #pragma unroll
    for (int off = 16; off > 0; off >>= 1)
        v += __shfl_xor_sync(0xFFFFFFFFu, v, off);
    return v;
}

__device__ __forceinline__ float dot8(float4 a, float4 b, float4 wa, float4 wb) {
    float s = a.x * wa.x;
    s = fmaf(a.y, wa.y, s);
    s = fmaf(a.z, wa.z, s);
    s = fmaf(a.w, wa.w, s);
    s = fmaf(b.x, wb.x, s);
    s = fmaf(b.y, wb.y, s);
    s = fmaf(b.z, wb.z, s);
    s = fmaf(b.w, wb.w, s);
    return s;
}

__global__ void __launch_bounds__(THREADS, BLOCKS_PER_SM)
gap_kernel(const float* __restrict__ x,
           const float* __restrict__ Ww,
           const float* __restrict__ Wb,
           float* __restrict__ out,
           int n_windows) {
    extern __shared__ char smem[];
    const int tid  = threadIdx.x;
    const int warp = tid >> 5;
    const int lane = tid & 31;
    const int n_warps = (int)((gridDim.x * blockDim.x) >> 5);
    const int warp_id = (blockIdx.x * blockDim.x + tid) >> 5;

    const uint32_t ring = smem_u32(smem) + warp * RING_BYTES;
    const float4*  ring4 = reinterpret_cast<const float4*>(smem + warp * RING_BYTES);

    // Weights: lane l owns features [4l,4l+4) and [128+4l,+4).
    const float4* Wv = reinterpret_cast<const float4*>(Ww);
    const float4 wa = Wv[lane], wb = Wv[lane + 32];
    const float bias = Wb[0];

    const int w0 = warp_id;               // first own window (2368 < 32768: always valid)
    const char* xc = (const char*)x;

    // Prologue: fill all 4 slots (clamp out-of-range to w0; data unused).
    #pragma unroll
    for (int d = 0; d < STAGES; d++) {
        int idx = w0 + d * n_warps;
        if (idx >= n_windows) idx = w0;
        issue_window(ring + d * WIN_BYTES, xc + (size_t)idx * WIN_BYTES, lane);
    }

    int iter = 0;
    for (int w = w0; w < n_windows; w += n_warps, iter++) {
        const int slot = iter & (STAGES - 1);

        // Oldest group (this slot) complete.
        cp_wait3();

        const float4* w4 = ring4 + slot * (WIN_BYTES / 16);
        float4 r0a = w4[lane],       r0b = w4[lane + 32];
        float4 r1a = w4[lane + 64],  r1b = w4[lane + 96];
        float4 r2a = w4[lane + 128], r2b = w4[lane + 160];

        // Per-lane partials: consumes all loaded registers, so the LDS reads
        // have completed before we overwrite the slot below.
        float p0 = dot8(r0a, r0b, wa, wb);
        float p1 = dot8(r1a, r1b, wa, wb);
        float p2 = dot8(r2a, r2b, wa, wb);

        // Refill this slot with window w + 4*stride (clamped; tail data unused).
        {
            int idx = w + STAGES * n_warps;
            if (idx >= n_windows) idx = w0;
            issue_window(ring + slot * WIN_BYTES, xc + (size_t)idx * WIN_BYTES, lane);
        }

        // Butterfly reductions + softmax over 3.
        float s0 = warp_reduce_sum(p0) + bias;
        float s1 = warp_reduce_sum(p1) + bias;
        float s2 = warp_reduce_sum(p2) + bias;

        float m = fmaxf(s0, fmaxf(s1, s2));
        float e0 = __expf(s0 - m);
        float e1 = __expf(s1 - m);
        float e2 = __expf(s2 - m);
        float inv = 1.0f / (e0 + e1 + e2);
        float a0 = e0 * inv, a1 = e1 * inv, a2 = e2 * inv;

        float4 oa, ob;
        oa.x = fmaf(r2a.x, a2, fmaf(r1a.x, a1, r0a.x * a0));
        oa.y = fmaf(r2a.y, a2, fmaf(r1a.y, a1, r0a.y * a0));
        oa.z = fmaf(r2a.z, a2, fmaf(r1a.z, a1, r0a.z * a0));
        oa.w = fmaf(r2a.w, a2, fmaf(r1a.w, a1, r0a.w * a0));
        ob.x = fmaf(r2b.x, a2, fmaf(r1b.x, a1, r0b.x * a0));
        ob.y = fmaf(r2b.y, a2, fmaf(r1b.y, a1, r0b.y * a0));
        ob.z = fmaf(r2b.z, a2, fmaf(r1b.z, a1, r0b.z * a0));
        ob.w = fmaf(r2b.w, a2, fmaf(r1b.w, a1, r0b.w * a0));

        float4* o4 = reinterpret_cast<float4*>(out + (size_t)w * 256);
        __stcs(o4 + lane,      oa);
        __stcs(o4 + lane + 32, ob);
    }
}

extern "C" void kernel_launch(void* const* d_in, const int* in_sizes, int n_in,
                              void* d_out, int out_size) {
    const float* x  = (const float*)d_in[0];  // [32, 3072, 256]
    const float* Ww = (const float*)d_in[1];  // [256]
    const float* Wb = (const float*)d_in[2];  // [1]
    float* out = (float*)d_out;               // [32, 1024, 256, 1]

    const int n_windows = in_sizes[0] / WIN_FLOATS;   // 32768

    cudaFuncSetAttribute(gap_kernel,
                         cudaFuncAttributeMaxDynamicSharedMemorySize, SMEM_BYTES);

    gap_kernel<<<NUM_SMS * BLOCKS_PER_SM, THREADS, SMEM_BYTES>>>(
        x, Ww, Wb, out, n_windows);
}

// round 7
// speedup vs baseline: 1.2092x; 1.2092x over previous
#include <cuda_runtime.h>

// GraphAttentionPooling: B=32, N=3072, F=256, P=3 -> S=1024, 32768 windows.
// Persistent exact-fit grid (148 SMs x 3 blocks x 8 warps = 3552 warps),
// grid-stride with depth-1 register prefetch (R3 topology) PLUS
// prefetch.global.L2 of the window PD iterations ahead: HBM->L2 is driven
// by registerless prefetches, so the __ldcs loads see ~L2 latency only.

#define F_DIM 256
#define P_DIM 3
#define NUM_SMS 148
#define BLOCKS_PER_SM 3
#define THREADS_PER_BLOCK 256
#define PD 4   // prefetch distance in grid-stride iterations

__device__ __forceinline__ float warp_reduce_sum(float v) {
    #pragma unroll
    for (int off = 16; off > 0; off >>= 1)
        v += __shfl_xor_sync(0xFFFFFFFFu, v, off);
    return v;
}

__device__ __forceinline__ float dot8(float4 a, float4 b, float4 wa, float4 wb) {
    float s = a.x * wa.x;
    s = fmaf(a.y, wa.y, s);
    s = fmaf(a.z, wa.z, s);
    s = fmaf(a.w, wa.w, s);
    s = fmaf(b.x, wb.x, s);
    s = fmaf(b.y, wb.y, s);
    s = fmaf(b.z, wb.z, s);
    s = fmaf(b.w, wb.w, s);
    return s;
}

__global__ void __launch_bounds__(THREADS_PER_BLOCK, BLOCKS_PER_SM)
gap_kernel(const float* __restrict__ x,
           const float* __restrict__ Ww,
           const float* __restrict__ Wb,
           float* __restrict__ out,
           int n_windows) {
    const int warp_id = (blockIdx.x * blockDim.x + threadIdx.x) >> 5;
    const int lane    = threadIdx.x & 31;
    const int n_warps = (int)((gridDim.x * blockDim.x) >> 5);

    const int fv = lane * 2;  // float4 index within a row (row = 64 float4)

    const float4* Wv = reinterpret_cast<const float4*>(Ww);
    const float4 wa = Wv[fv], wb = Wv[fv + 1];
    const float bias = Wb[0];

    const float4* xbase = reinterpret_cast<const float4*>(x);
    float4*       obase = reinterpret_cast<float4*>(out);

    int w = warp_id;
    if (w >= n_windows) return;

    // L2-prefetch the first PD windows of this warp's stream (lanes 0..23,
    // one 128B line each; window = 3072B = 24 lines).
    if (lane < 24) {
        #pragma unroll
        for (int d = 0; d < PD; d++) {
            long long wi = w + (long long)d * n_warps;
            if (wi < n_windows) {
                const char* p = (const char*)x + wi * 3072 + lane * 128;
                asm volatile("prefetch.global.L2 [%0];" :: "l"(p));
            }
        }
    }

    // Register prefetch of window 0 (window stride = 192 float4).
    const float4* xin0 = xbase + (long long)w * 192 + fv;
    float4 n0a = __ldcs(xin0 + 0 * 64), n0b = __ldcs(xin0 + 0 * 64 + 1);
    float4 n1a = __ldcs(xin0 + 1 * 64), n1b = __ldcs(xin0 + 1 * 64 + 1);
    float4 n2a = __ldcs(xin0 + 2 * 64), n2b = __ldcs(xin0 + 2 * 64 + 1);

    for (; w < n_windows; w += n_warps) {
        // L2-prefetch the window PD iterations ahead (registerless).
        {
            long long wp = w + (long long)PD * n_warps;
            if (wp < n_windows && lane < 24) {
                const char* p = (const char*)x + wp * 3072 + lane * 128;
                asm volatile("prefetch.global.L2 [%0];" :: "l"(p));
            }
        }

        // Current window = last register prefetch.
        float4 r0a = n0a, r0b = n0b;
        float4 r1a = n1a, r1b = n1b;
        float4 r2a = n2a, r2b = n2b;

        // Register prefetch of next window BEFORE the dependent compute chain.
        {
            int wn = w + n_warps;
            wn = (wn < n_windows) ? wn : w;  // last iter: reload self (L2 hit)
            const float4* nx = xbase + (long long)wn * 192 + fv;
            n0a = __ldcs(nx + 0 * 64); n0b = __ldcs(nx + 0 * 64 + 1);
            n1a = __ldcs(nx + 1 * 64); n1b = __ldcs(nx + 1 * 64 + 1);
            n2a = __ldcs(nx + 2 * 64); n2b = __ldcs(nx + 2 * 64 + 1);
        }

        // Scores: per-lane partials + butterfly reduce.
        float s0 = warp_reduce_sum(dot8(r0a, r0b, wa, wb)) + bias;
        float s1 = warp_reduce_sum(dot8(r1a, r1b, wa, wb)) + bias;
        float s2 = warp_reduce_sum(dot8(r2a, r2b, wa, wb)) + bias;

        // Softmax over 3 scores.
        float m = fmaxf(s0, fmaxf(s1, s2));
        float e0 = __expf(s0 - m);
        float e1 = __expf(s1 - m);
        float e2 = __expf(s2 - m);
        float inv = 1.0f / (e0 + e1 + e2);
        float a0 = e0 * inv, a1 = e1 * inv, a2 = e2 * inv;

        // Weighted combine.
        float4 oa, ob;
        oa.x = fmaf(r2a.x, a2, fmaf(r1a.x, a1, r0a.x * a0));
        oa.y = fmaf(r2a.y, a2, fmaf(r1a.y, a1, r0a.y * a0));
        oa.z = fmaf(r2a.z, a2, fmaf(r1a.z, a1, r0a.z * a0));
        oa.w = fmaf(r2a.w, a2, fmaf(r1a.w, a1, r0a.w * a0));
        ob.x = fmaf(r2b.x, a2, fmaf(r1b.x, a1, r0b.x * a0));
        ob.y = fmaf(r2b.y, a2, fmaf(r1b.y, a1, r0b.y * a0));
        ob.z = fmaf(r2b.z, a2, fmaf(r1b.z, a1, r0b.z * a0));
        ob.w = fmaf(r2b.w, a2, fmaf(r1b.w, a1, r0b.w * a0));

        float4* o = obase + (long long)w * 64 + fv;
        __stcs(o,     oa);
        __stcs(o + 1, ob);
    }
}

extern "C" void kernel_launch(void* const* d_in, const int* in_sizes, int n_in,
                              void* d_out, int out_size) {
    const float* x  = (const float*)d_in[0];  // [32, 3072, 256]
    const float* Ww = (const float*)d_in[1];  // [256]
    const float* Wb = (const float*)d_in[2];  // [1]
    float* out = (float*)d_out;               // [32, 1024, 256, 1]

    const int n_windows = in_sizes[0] / (P_DIM * F_DIM);  // 32768
    const int blocks = NUM_SMS * BLOCKS_PER_SM;           // 444, exact-fit one wave

    gap_kernel<<<blocks, THREADS_PER_BLOCK>>>(x, Ww, Wb, out, n_windows);
}